// round 10
// baseline (speedup 1.0000x reference)
#include <cuda_runtime.h>
#include <cuda_fp16.h>
#include <math.h>
#include <stdint.h>

// ===========================================================================
// GNN over fixed 4-node graph, B=32768 (M = 4B = 131072 rows).
// GEMM: mma.sync fp16 -> fp32, CTA tile 128x256, warp tile 64x64 (8 warps).
// smem-traffic-optimized (ldsm_x4 for A and B), 3-stage cp.async pipeline.
// GCN post fused into L1 epilogue; SAGE posts separate. fp16 activations.
// ===========================================================================

#define MAXB 32768
#define PADK 72                  // 64 + 8 pad (fp16)
#define TILE_A (128 * PADK * 2)  // 18432 B
#define TILE_W (256 * PADK * 2)  // 36864 B
#define STAGE_B (TILE_A + TILE_W)
#define STAGES 3
#define SMEM_BYTES (STAGES * STAGE_B)   // 165888
#define PADE 264                 // epilogue staging stride (fp16 units)

__device__ float g_A[16];   // GCN normalized adjacency (4x4)
__device__ float g_M[16];   // SAGE mean-aggregation matrix (4x4)
__device__ __align__(16) __half g_Pf[(size_t)MAXB * 4 * 1024];
__device__ __align__(16) __half g_hf[(size_t)MAXB * 4 * 1024];
__device__ __align__(16) __half g_wt[1507328];

// ---------------------------------------------------------------------------
__device__ __forceinline__ uint32_t smem_u32(const void* p) {
    uint32_t a;
    asm("{ .reg .u64 t; cvta.to.shared.u64 t, %1; cvt.u32.u64 %0, t; }"
        : "=r"(a) : "l"(p));
    return a;
}
__device__ __forceinline__ void ldsm_x4(uint32_t (&r)[4], uint32_t addr) {
    asm volatile("ldmatrix.sync.aligned.m8n8.x4.shared.b16 {%0,%1,%2,%3}, [%4];"
                 : "=r"(r[0]), "=r"(r[1]), "=r"(r[2]), "=r"(r[3]) : "r"(addr));
}
__device__ __forceinline__ void mma_f16(float (&d)[4], const uint32_t (&a)[4],
                                        uint32_t b0, uint32_t b1) {
    asm volatile(
        "mma.sync.aligned.m16n8k16.row.col.f32.f16.f16.f32 "
        "{%0,%1,%2,%3}, {%4,%5,%6,%7}, {%8,%9}, {%0,%1,%2,%3};"
        : "+f"(d[0]), "+f"(d[1]), "+f"(d[2]), "+f"(d[3])
        : "r"(a[0]), "r"(a[1]), "r"(a[2]), "r"(a[3]), "r"(b0), "r"(b1));
}
__device__ __forceinline__ void cp_async16(uint32_t dst, const void* src) {
    asm volatile("cp.async.cg.shared.global [%0], [%1], 16;"
                 :: "r"(dst), "l"(src));
}
#define CP_COMMIT() asm volatile("cp.async.commit_group;" ::: "memory")
#define CP_WAIT1()  asm volatile("cp.async.wait_group 1;" ::: "memory")

__device__ __forceinline__ uint32_t h2pack(float a, float b) {
    __half2 h = __floats2half2_rn(a, b);
    return *(uint32_t*)&h;
}
__device__ __forceinline__ void store_h4(__half* H, size_t e, float4 v) {
    *(uint2*)(H + e) = make_uint2(h2pack(v.x, v.y), h2pack(v.z, v.w));
}
__device__ __forceinline__ float4 load_h4(const __half* H, size_t e) {
    uint2 u = *(const uint2*)(H + e);
    __half2 p0 = *(__half2*)&u.x, p1 = *(__half2*)&u.y;
    float2 a = __half22float2(p0), b = __half22float2(p1);
    return make_float4(a.x, a.y, b.x, b.y);
}

// ---------------------------------------------------------------------------
// Build 4x4 mixing matrices from edge_index (dtype-adaptive int32/int64).
// ---------------------------------------------------------------------------
__global__ void build_graph_kernel(const void* __restrict__ ei_raw, int E)
{
    if (threadIdx.x != 0 || blockIdx.x != 0) return;
    const long long* e64 = (const long long*)ei_raw;
    const int*       e32 = (const int*)ei_raw;
    bool is64 = true;
    for (int e = 0; e < E; ++e) {
        long long v = e64[e];
        if (v < 0 || v >= 4) { is64 = false; break; }
    }
    int src[64], dst[64];
    for (int e = 0; e < E; ++e) {
        if (is64) { src[e] = (int)e64[e]; dst[e] = (int)e64[E + e]; }
        else      { src[e] = e32[e];      dst[e] = e32[E + e]; }
    }
    float degG[4] = {1.f, 1.f, 1.f, 1.f};
    float cntS[4] = {0.f, 0.f, 0.f, 0.f};
    for (int e = 0; e < E; ++e) { degG[dst[e]] += 1.f; cntS[dst[e]] += 1.f; }
    float dinv[4];
    #pragma unroll
    for (int n = 0; n < 4; ++n) dinv[n] = rsqrtf(degG[n]);
    float A[16], M[16];
    #pragma unroll
    for (int i = 0; i < 16; ++i) { A[i] = 0.f; M[i] = 0.f; }
    for (int e = 0; e < E; ++e) {
        int s = src[e], d = dst[e];
        A[d * 4 + s] += dinv[s] * dinv[d];
        M[d * 4 + s] += 1.f / fmaxf(cntS[d], 1.f);
    }
    #pragma unroll
    for (int n = 0; n < 4; ++n) A[n * 4 + n] += dinv[n] * dinv[n];
    #pragma unroll
    for (int i = 0; i < 16; ++i) { g_A[i] = A[i]; g_M[i] = M[i]; }
}

// ---------------------------------------------------------------------------
__global__ void prep_w_kernel(const float* __restrict__ W, int K0, int N,
                              size_t dst_off)
{
    long long idx = (long long)blockIdx.x * 256 + threadIdx.x;
    if (idx >= (long long)K0 * N) return;
    int k = (int)(idx / N), n = (int)(idx % N);
    g_wt[dst_off + (size_t)n * K0 + k] = __float2half_rn(W[idx]);
}

__global__ void split_x_kernel(const float* __restrict__ X, long long n4)
{
    long long i = (long long)blockIdx.x * 256 + threadIdx.x;
    if (i >= n4) return;
    float4 v = ((const float4*)X)[i];
    store_h4(g_Pf, (size_t)i * 4, v);
}

// ---------------------------------------------------------------------------
// fp16 GEMM: out[M,Ntot] = A[M,K0] @ W[K0,Ntot].
// CTA tile 128x256, 8 warps (2x4) of 64x64. 3-stage cp.async, wait_group 1.
// post=0: coalesced fp16 P store; post=1: fused GCN (mix+bias+relu).
// ---------------------------------------------------------------------------
__global__ __launch_bounds__(256, 1)
void gemm_tc_kernel(const __half* __restrict__ Ain, size_t w_off,
                    __half* __restrict__ Out, const float* __restrict__ bias,
                    int K0, int Ntot, int post)
{
    extern __shared__ char smem[];
    const uint32_t sbase = smem_u32(smem);
    const int tid = threadIdx.x, wid = tid >> 5, lid = tid & 31;
    const int by = blockIdx.x, bm = blockIdx.y;
    const int warp_m = wid & 1, warp_n = wid >> 1;
    const int m_base = warp_m * 64, n_base = warp_n * 64;

    float acc[4][8][4];
    #pragma unroll
    for (int mt = 0; mt < 4; ++mt)
        #pragma unroll
        for (int nt = 0; nt < 8; ++nt)
            #pragma unroll
            for (int i = 0; i < 4; ++i) acc[mt][nt][i] = 0.f;

    // A ldsm lane addressing
    const int a_r  = lid & 15;
    const int a_ko = (lid >> 4) << 3;
    // B ldsm_x4 lane addressing: r0=(n0-7,k0) r1=(n0-7,k8) r2=(n8-15,k0) r3=(n8-15,k8)
    const int b_n  = (lid & 7) + ((lid >> 4) << 3);
    const int b_ko = ((lid >> 3) & 1) << 3;

    const int KC = K0 >> 6;
    const __half* Ab = Ain + (size_t)bm * 128 * K0;
    const __half* Wb = g_wt + w_off + (size_t)by * 256 * K0;

    auto prefetch = [&](int kc) {
        uint32_t sb = sbase + (kc % STAGES) * STAGE_B;
        #pragma unroll
        for (int i = 0; i < 4; ++i) {      // A: 1024 lines
            int c = tid + i * 256, r = c >> 3, q = c & 7;
            cp_async16(sb + (uint32_t)(r * PADK + q * 8) * 2,
                       Ab + (size_t)r * K0 + (size_t)kc * 64 + q * 8);
        }
        #pragma unroll
        for (int i = 0; i < 8; ++i) {      // W: 2048 lines
            int c = tid + i * 256, r = c >> 3, q = c & 7;
            cp_async16(sb + TILE_A + (uint32_t)(r * PADK + q * 8) * 2,
                       Wb + (size_t)r * K0 + (size_t)kc * 64 + q * 8);
        }
        CP_COMMIT();
    };

    prefetch(0);
    if (KC > 1) prefetch(1); else CP_COMMIT();

    for (int kc = 0; kc < KC; ++kc) {
        CP_WAIT1();
        __syncthreads();
        if (kc + 2 < KC) prefetch(kc + 2); else CP_COMMIT();

        const uint32_t sb = sbase + (kc % STAGES) * STAGE_B;
        #pragma unroll
        for (int ks = 0; ks < 4; ++ks) {
            const int kof = ks * 16;
            uint32_t bf[4][4];
            #pragma unroll
            for (int p = 0; p < 4; ++p) {
                uint32_t boff = (uint32_t)((n_base + p * 16 + b_n) * PADK
                                           + kof + b_ko) * 2;
                ldsm_x4(bf[p], sb + TILE_A + boff);
            }
            #pragma unroll
            for (int mt = 0; mt < 4; ++mt) {
                uint32_t aoff = (uint32_t)((m_base + mt * 16 + a_r) * PADK
                                           + kof + a_ko) * 2;
                uint32_t ah[4];
                ldsm_x4(ah, sb + aoff);
                #pragma unroll
                for (int p = 0; p < 4; ++p) {
                    mma_f16(acc[mt][2 * p],     ah, bf[p][0], bf[p][1]);
                    mma_f16(acc[mt][2 * p + 1], ah, bf[p][2], bf[p][3]);
                }
            }
        }
    }

    // ---- epilogue: stage fp16 tile [128][PADE] in smem ----
    __syncthreads();
    {
        const int rq = lid >> 2, cq = (lid & 3) * 2;
        #pragma unroll
        for (int mt = 0; mt < 4; ++mt) {
            #pragma unroll
            for (int nt = 0; nt < 8; ++nt) {
                int col = n_base + nt * 8 + cq;
                int r0 = m_base + mt * 16 + rq;
                *(uint32_t*)(smem + (r0 * PADE + col) * 2) =
                    h2pack(acc[mt][nt][0], acc[mt][nt][1]);
                *(uint32_t*)(smem + ((r0 + 8) * PADE + col) * 2) =
                    h2pack(acc[mt][nt][2], acc[mt][nt][3]);
            }
        }
    }
    __syncthreads();

    if (post == 0) {
        // coalesced 128-bit stores: 32 lanes cover one 256-col row
        const int rbase = tid >> 5, cg = (tid & 31) * 8;
        #pragma unroll
        for (int it = 0; it < 16; ++it) {
            int row = rbase + it * 8;
            uint4 v = *(uint4*)(smem + (row * PADE + cg) * 2);
            *(uint4*)(Out + ((size_t)bm * 128 + row) * Ntot
                          + (size_t)by * 256 + cg) = v;
        }
    } else {
        // GCN: y[n] = relu( sum_m A[n,m] * P[b*4+m] + bias ); Ntot == 1024
        float mat[16];
        #pragma unroll
        for (int i = 0; i < 16; ++i) mat[i] = g_A[i];
        #pragma unroll
        for (int it = 0; it < 4; ++it) {
            int item = it * 256 + tid;        // 0..1023
            int b = item >> 5, ch = item & 31;
            int colg = by * 256 + ch * 8;
            float4 bv0 = *(const float4*)(bias + colg);
            float4 bv1 = *(const float4*)(bias + colg + 4);
            float bb[8] = {bv0.x, bv0.y, bv0.z, bv0.w, bv1.x, bv1.y, bv1.z, bv1.w};
            float v[4][8];
            #pragma unroll
            for (int m = 0; m < 4; ++m) {
                uint4 u = *(uint4*)(smem + ((b * 4 + m) * PADE + ch * 8) * 2);
                uint32_t* up = (uint32_t*)&u;
                #pragma unroll
                for (int q = 0; q < 4; ++q) {
                    float2 f = __half22float2(*(__half2*)&up[q]);
                    v[m][q * 2] = f.x; v[m][q * 2 + 1] = f.y;
                }
            }
            #pragma unroll
            for (int n = 0; n < 4; ++n) {
                uint32_t o[4];
                #pragma unroll
                for (int q = 0; q < 4; ++q) {
                    float y0 = fmaxf(mat[n*4+0]*v[0][q*2]   + mat[n*4+1]*v[1][q*2]
                                   + mat[n*4+2]*v[2][q*2]   + mat[n*4+3]*v[3][q*2]
                                   + bb[q*2], 0.f);
                    float y1 = fmaxf(mat[n*4+0]*v[0][q*2+1] + mat[n*4+1]*v[1][q*2+1]
                                   + mat[n*4+2]*v[2][q*2+1] + mat[n*4+3]*v[3][q*2+1]
                                   + bb[q*2+1], 0.f);
                    o[q] = h2pack(y0, y1);
                }
                size_t row = (size_t)bm * 128 + b * 4 + n;
                *(uint4*)(Out + row * 1024 + colg) = *(uint4*)o;
            }
        }
    }
}

// ---------------------------------------------------------------------------
// SAGE post: P[M, 2N] = [Pl | Pr], fp16.  h[b,n,:] =
//   relu( l2norm( Mix.Pl[b,:,:] (row n) + Pr[b,n,:] + bias ) ), fp16 out.
// ---------------------------------------------------------------------------
__global__ void sage_post_kernel(const float* __restrict__ bias, int N)
{
    __shared__ float red[4][4];
    const int b = blockIdx.x, tid = threadIdx.x;
    const int wid = tid >> 5, lane = tid & 31;
    const int nw = blockDim.x >> 5;
    float mat[16];
    #pragma unroll
    for (int i = 0; i < 16; ++i) mat[i] = g_M[i];

    const size_t Pb = (size_t)b * 4 * (2 * N);
    const int f = tid * 4;
    float4 pl[4];
    #pragma unroll
    for (int m = 0; m < 4; ++m)
        pl[m] = load_h4(g_Pf, Pb + (size_t)m * 2 * N + f);
    float4 bv = *(const float4*)(bias + f);

    float4 y[4];
    float ss[4];
    #pragma unroll
    for (int n = 0; n < 4; ++n) {
        float4 pr = load_h4(g_Pf, Pb + (size_t)n * 2 * N + N + f);
        float4 r;
        r.x = mat[n*4+0]*pl[0].x + mat[n*4+1]*pl[1].x + mat[n*4+2]*pl[2].x + mat[n*4+3]*pl[3].x + pr.x + bv.x;
        r.y = mat[n*4+0]*pl[0].y + mat[n*4+1]*pl[1].y + mat[n*4+2]*pl[2].y + mat[n*4+3]*pl[3].y + pr.y + bv.y;
        r.z = mat[n*4+0]*pl[0].z + mat[n*4+1]*pl[1].z + mat[n*4+2]*pl[2].z + mat[n*4+3]*pl[3].z + pr.z + bv.z;
        r.w = mat[n*4+0]*pl[0].w + mat[n*4+1]*pl[1].w + mat[n*4+2]*pl[2].w + mat[n*4+3]*pl[3].w + pr.w + bv.w;
        y[n] = r;
        ss[n] = r.x * r.x + r.y * r.y + r.z * r.z + r.w * r.w;
    }
    #pragma unroll
    for (int n = 0; n < 4; ++n)
        #pragma unroll
        for (int off = 16; off > 0; off >>= 1)
            ss[n] += __shfl_xor_sync(0xffffffffu, ss[n], off);
    if (lane == 0) {
        #pragma unroll
        for (int n = 0; n < 4; ++n) red[n][wid] = ss[n];
    }
    __syncthreads();
    float inv[4];
    #pragma unroll
    for (int n = 0; n < 4; ++n) {
        float t = 0.f;
        for (int w = 0; w < nw; ++w) t += red[n][w];
        inv[n] = 1.f / fmaxf(sqrtf(t), 1e-12f);
    }
    #pragma unroll
    for (int n = 0; n < 4; ++n) {
        float4 o;
        o.x = fmaxf(y[n].x * inv[n], 0.f);
        o.y = fmaxf(y[n].y * inv[n], 0.f);
        o.z = fmaxf(y[n].z * inv[n], 0.f);
        o.w = fmaxf(y[n].w * inv[n], 0.f);
        store_h4(g_hf, (size_t)(b * 4 + n) * N + f, o);
    }
}

// ---------------------------------------------------------------------------
// FC [B,1024] @ Wfc[1024,10] + bfc, softmax. One warp per batch row.
// ---------------------------------------------------------------------------
__global__ void fc_softmax_kernel(const float* __restrict__ Wfc,
                                  const float* __restrict__ bfc,
                                  float* __restrict__ out, int B)
{
    long long warp = ((long long)blockIdx.x * blockDim.x + threadIdx.x) >> 5;
    int lane = threadIdx.x & 31;
    if (warp >= B) return;
    const size_t base = (size_t)warp * 1024;
    float acc[10];
    #pragma unroll
    for (int o = 0; o < 10; ++o) acc[o] = 0.f;
    for (int k = lane; k < 1024; k += 32) {
        float hv = __half2float(g_hf[base + k]);
        const float* w = Wfc + (size_t)k * 10;
        #pragma unroll
        for (int o = 0; o < 10; ++o) acc[o] += hv * w[o];
    }
    #pragma unroll
    for (int o = 0; o < 10; ++o)
        #pragma unroll
        for (int off = 16; off > 0; off >>= 1)
            acc[o] += __shfl_xor_sync(0xffffffffu, acc[o], off);
    if (lane == 0) {
        float logit[10], m = -1e30f;
        #pragma unroll
        for (int o = 0; o < 10; ++o) {
            logit[o] = acc[o] + bfc[o];
            m = fmaxf(m, logit[o]);
        }
        float s = 0.f;
        #pragma unroll
        for (int o = 0; o < 10; ++o) { logit[o] = expf(logit[o] - m); s += logit[o]; }
        float invs = 1.f / s;
        float* orow = out + (size_t)warp * 10;
        #pragma unroll
        for (int o = 0; o < 10; ++o) orow[o] = logit[o] * invs;
    }
}

// ---------------------------------------------------------------------------
extern "C" void kernel_launch(void* const* d_in, const int* in_sizes, int n_in,
                              void* d_out, int out_size)
{
    const float* x   = (const float*)d_in[0];
    const void*  ei  = d_in[1];
    const float* W1  = (const float*)d_in[2];
    const float* b1  = (const float*)d_in[3];
    const float* Wl2 = (const float*)d_in[4];
    const float* bl2 = (const float*)d_in[5];
    const float* Wr2 = (const float*)d_in[6];
    const float* Wl3 = (const float*)d_in[7];
    const float* bl3 = (const float*)d_in[8];
    const float* Wr3 = (const float*)d_in[9];
    const float* Wl4 = (const float*)d_in[10];
    const float* bl4 = (const float*)d_in[11];
    const float* Wr4 = (const float*)d_in[12];
    const float* Wfc = (const float*)d_in[13];
    const float* bfc = (const float*)d_in[14];

    const int B = in_sizes[0] / (4 * 64);
    const int E = in_sizes[1] / 2;
    const long long M = (long long)B * 4;

    __half *Pf, *hf;
    cudaGetSymbolAddress((void**)&Pf, g_Pf);
    cudaGetSymbolAddress((void**)&hf, g_hf);

    cudaFuncSetAttribute(gemm_tc_kernel,
                         cudaFuncAttributeMaxDynamicSharedMemorySize, SMEM_BYTES);

    build_graph_kernel<<<1, 32>>>(ei, E);

    // weight prep: N-concat layout [Ntot][K0], offsets in fp16 elements
    const size_t OW1 = 0;                       // [1024][64]
    const size_t OW2 = 65536;                   // [1024][1024] = [Wl2|Wr2]
    const size_t OW3 = OW2 + 1048576;           // [512][512]  = [Wl3|Wr3]
    const size_t OW4 = OW3 + 262144;            // [512][256]  = [Wl4|Wr4]
    prep_w_kernel<<<(64   * 1024 + 255) / 256, 256>>>(W1,  64,   1024, OW1);
    prep_w_kernel<<<(1024 * 512  + 255) / 256, 256>>>(Wl2, 1024, 512,  OW2);
    prep_w_kernel<<<(1024 * 512  + 255) / 256, 256>>>(Wr2, 1024, 512,  OW2 + (size_t)512 * 1024);
    prep_w_kernel<<<(512  * 256  + 255) / 256, 256>>>(Wl3, 512,  256,  OW3);
    prep_w_kernel<<<(512  * 256  + 255) / 256, 256>>>(Wr3, 512,  256,  OW3 + (size_t)256 * 512);
    prep_w_kernel<<<(256  * 256  + 255) / 256, 256>>>(Wl4, 256,  256,  OW4);
    prep_w_kernel<<<(256  * 256  + 255) / 256, 256>>>(Wr4, 256,  256,  OW4 + (size_t)256 * 256);

    const unsigned gm = (unsigned)(M / 128);

    // x -> fp16 (into g_Pf, the L1 GEMM input)
    split_x_kernel<<<(unsigned)((M * 16 + 255) / 256), 256>>>(x, M * 16);
    // L1: h1 = relu(Mix.(x@W1) + b1) — GCN fused epilogue
    gemm_tc_kernel<<<dim3(4, gm), 256, SMEM_BYTES>>>(Pf, OW1, hf, b1, 64, 1024, 1);
    // L2: P2 = h1 @ [Wl2|Wr2] [M,1024];  h2 = sage_post(P2) [M,512]
    gemm_tc_kernel<<<dim3(4, gm), 256, SMEM_BYTES>>>(hf, OW2, Pf, b1, 1024, 1024, 0);
    sage_post_kernel<<<B, 128>>>(bl2, 512);
    // L3: P3 = h2 @ [Wl3|Wr3] [M,512];  h3 [M,256]
    gemm_tc_kernel<<<dim3(2, gm), 256, SMEM_BYTES>>>(hf, OW3, Pf, b1, 512, 512, 0);
    sage_post_kernel<<<B, 64>>>(bl3, 256);
    // L4: P4 = h3 @ [Wl4|Wr4] [M,512];  h4 [M,256]
    gemm_tc_kernel<<<dim3(2, gm), 256, SMEM_BYTES>>>(hf, OW4, Pf, b1, 256, 512, 0);
    sage_post_kernel<<<B, 64>>>(bl4, 256);
    // FC + softmax
    fc_softmax_kernel<<<(unsigned)((B * 32 + 255) / 256), 256>>>(
        Wfc, bfc, (float*)d_out, B);
}

// round 11
// speedup vs baseline: 1.0722x; 1.0722x over previous
#include <cuda_runtime.h>
#include <cuda_fp16.h>
#include <math.h>
#include <stdint.h>

// ===========================================================================
// GNN over fixed 4-node graph, B=32768 (M = 4B = 131072 rows).
// GEMM: mma.sync fp16 -> fp32. CTA tile 128x128 with 4 warps (2x2) of
// 64x64 — 128 B/MMA smem fragment traffic AND 2 CTAs/SM for sync overlap.
// 3-stage cp.async pipeline. GCN post fused into L1 epilogue.
// ===========================================================================

#define MAXB 32768
#define PADK 72                  // 64 + 8 pad (fp16)
#define TILE_A (128 * PADK * 2)  // 18432 B
#define TILE_W (128 * PADK * 2)  // 18432 B
#define STAGE_B (TILE_A + TILE_W)
#define STAGES 3
#define SMEM_BYTES (STAGES * STAGE_B)   // 110592 -> 2 CTAs/SM
#define PADE 136                 // epilogue staging stride (fp16 units)
#define NTHREADS 128

__device__ float g_A[16];   // GCN normalized adjacency (4x4)
__device__ float g_M[16];   // SAGE mean-aggregation matrix (4x4)
__device__ __align__(16) __half g_Pf[(size_t)MAXB * 4 * 1024];
__device__ __align__(16) __half g_hf[(size_t)MAXB * 4 * 1024];
__device__ __align__(16) __half g_wt[1507328];

// ---------------------------------------------------------------------------
__device__ __forceinline__ uint32_t smem_u32(const void* p) {
    uint32_t a;
    asm("{ .reg .u64 t; cvta.to.shared.u64 t, %1; cvt.u32.u64 %0, t; }"
        : "=r"(a) : "l"(p));
    return a;
}
__device__ __forceinline__ void ldsm_x4(uint32_t (&r)[4], uint32_t addr) {
    asm volatile("ldmatrix.sync.aligned.m8n8.x4.shared.b16 {%0,%1,%2,%3}, [%4];"
                 : "=r"(r[0]), "=r"(r[1]), "=r"(r[2]), "=r"(r[3]) : "r"(addr));
}
__device__ __forceinline__ void mma_f16(float (&d)[4], const uint32_t (&a)[4],
                                        uint32_t b0, uint32_t b1) {
    asm volatile(
        "mma.sync.aligned.m16n8k16.row.col.f32.f16.f16.f32 "
        "{%0,%1,%2,%3}, {%4,%5,%6,%7}, {%8,%9}, {%0,%1,%2,%3};"
        : "+f"(d[0]), "+f"(d[1]), "+f"(d[2]), "+f"(d[3])
        : "r"(a[0]), "r"(a[1]), "r"(a[2]), "r"(a[3]), "r"(b0), "r"(b1));
}
__device__ __forceinline__ void cp_async16(uint32_t dst, const void* src) {
    asm volatile("cp.async.cg.shared.global [%0], [%1], 16;"
                 :: "r"(dst), "l"(src));
}
#define CP_COMMIT() asm volatile("cp.async.commit_group;" ::: "memory")
#define CP_WAIT1()  asm volatile("cp.async.wait_group 1;" ::: "memory")

__device__ __forceinline__ uint32_t h2pack(float a, float b) {
    __half2 h = __floats2half2_rn(a, b);
    return *(uint32_t*)&h;
}
__device__ __forceinline__ void store_h4(__half* H, size_t e, float4 v) {
    *(uint2*)(H + e) = make_uint2(h2pack(v.x, v.y), h2pack(v.z, v.w));
}
__device__ __forceinline__ float4 load_h4(const __half* H, size_t e) {
    uint2 u = *(const uint2*)(H + e);
    __half2 p0 = *(__half2*)&u.x, p1 = *(__half2*)&u.y;
    float2 a = __half22float2(p0), b = __half22float2(p1);
    return make_float4(a.x, a.y, b.x, b.y);
}

// ---------------------------------------------------------------------------
// Build 4x4 mixing matrices from edge_index (dtype-adaptive int32/int64).
// ---------------------------------------------------------------------------
__global__ void build_graph_kernel(const void* __restrict__ ei_raw, int E)
{
    if (threadIdx.x != 0 || blockIdx.x != 0) return;
    const long long* e64 = (const long long*)ei_raw;
    const int*       e32 = (const int*)ei_raw;
    bool is64 = true;
    for (int e = 0; e < E; ++e) {
        long long v = e64[e];
        if (v < 0 || v >= 4) { is64 = false; break; }
    }
    int src[64], dst[64];
    for (int e = 0; e < E; ++e) {
        if (is64) { src[e] = (int)e64[e]; dst[e] = (int)e64[E + e]; }
        else      { src[e] = e32[e];      dst[e] = e32[E + e]; }
    }
    float degG[4] = {1.f, 1.f, 1.f, 1.f};
    float cntS[4] = {0.f, 0.f, 0.f, 0.f};
    for (int e = 0; e < E; ++e) { degG[dst[e]] += 1.f; cntS[dst[e]] += 1.f; }
    float dinv[4];
    #pragma unroll
    for (int n = 0; n < 4; ++n) dinv[n] = rsqrtf(degG[n]);
    float A[16], M[16];
    #pragma unroll
    for (int i = 0; i < 16; ++i) { A[i] = 0.f; M[i] = 0.f; }
    for (int e = 0; e < E; ++e) {
        int s = src[e], d = dst[e];
        A[d * 4 + s] += dinv[s] * dinv[d];
        M[d * 4 + s] += 1.f / fmaxf(cntS[d], 1.f);
    }
    #pragma unroll
    for (int n = 0; n < 4; ++n) A[n * 4 + n] += dinv[n] * dinv[n];
    #pragma unroll
    for (int i = 0; i < 16; ++i) { g_A[i] = A[i]; g_M[i] = M[i]; }
}

// ---------------------------------------------------------------------------
__global__ void prep_w_kernel(const float* __restrict__ W, int K0, int N,
                              size_t dst_off)
{
    long long idx = (long long)blockIdx.x * 256 + threadIdx.x;
    if (idx >= (long long)K0 * N) return;
    int k = (int)(idx / N), n = (int)(idx % N);
    g_wt[dst_off + (size_t)n * K0 + k] = __float2half_rn(W[idx]);
}

__global__ void split_x_kernel(const float* __restrict__ X, long long n4)
{
    long long i = (long long)blockIdx.x * 256 + threadIdx.x;
    if (i >= n4) return;
    float4 v = ((const float4*)X)[i];
    store_h4(g_Pf, (size_t)i * 4, v);
}

// ---------------------------------------------------------------------------
// fp16 GEMM: out[M,Ntot] = A[M,K0] @ W[K0,Ntot].
// CTA 128x128, 4 warps (2x2) of 64x64. 3-stage cp.async, wait_group 1.
// post=0: coalesced fp16 P store; post=1: fused GCN (mix+bias+relu).
// ---------------------------------------------------------------------------
__global__ __launch_bounds__(NTHREADS, 2)
void gemm_tc_kernel(const __half* __restrict__ Ain, size_t w_off,
                    __half* __restrict__ Out, const float* __restrict__ bias,
                    int K0, int Ntot, int post)
{
    extern __shared__ char smem[];
    const uint32_t sbase = smem_u32(smem);
    const int tid = threadIdx.x, wid = tid >> 5, lid = tid & 31;
    const int by = blockIdx.x, bm = blockIdx.y;
    const int warp_m = wid & 1, warp_n = wid >> 1;   // 2 x 2 warps
    const int m_base = warp_m * 64, n_base = warp_n * 64;

    float acc[4][8][4];
    #pragma unroll
    for (int mt = 0; mt < 4; ++mt)
        #pragma unroll
        for (int nt = 0; nt < 8; ++nt)
            #pragma unroll
            for (int i = 0; i < 4; ++i) acc[mt][nt][i] = 0.f;

    const int a_r  = lid & 15;
    const int a_ko = (lid >> 4) << 3;
    const int b_n  = (lid & 7) + ((lid >> 4) << 3);
    const int b_ko = ((lid >> 3) & 1) << 3;

    const int KC = K0 >> 6;
    const __half* Ab = Ain + (size_t)bm * 128 * K0;
    const __half* Wb = g_wt + w_off + (size_t)by * 128 * K0;

    auto prefetch = [&](int kc) {
        uint32_t sb = sbase + (kc % STAGES) * STAGE_B;
        #pragma unroll
        for (int i = 0; i < 8; ++i) {      // A: 1024 lines / 128 thr
            int c = tid + i * NTHREADS, r = c >> 3, q = c & 7;
            cp_async16(sb + (uint32_t)(r * PADK + q * 8) * 2,
                       Ab + (size_t)r * K0 + (size_t)kc * 64 + q * 8);
        }
        #pragma unroll
        for (int i = 0; i < 8; ++i) {      // W: 1024 lines / 128 thr
            int c = tid + i * NTHREADS, r = c >> 3, q = c & 7;
            cp_async16(sb + TILE_A + (uint32_t)(r * PADK + q * 8) * 2,
                       Wb + (size_t)r * K0 + (size_t)kc * 64 + q * 8);
        }
        CP_COMMIT();
    };

    prefetch(0);
    if (KC > 1) prefetch(1); else CP_COMMIT();

    for (int kc = 0; kc < KC; ++kc) {
        CP_WAIT1();
        __syncthreads();
        if (kc + 2 < KC) prefetch(kc + 2); else CP_COMMIT();

        const uint32_t sb = sbase + (kc % STAGES) * STAGE_B;
        #pragma unroll
        for (int ks = 0; ks < 4; ++ks) {
            const int kof = ks * 16;
            uint32_t bf[4][4];
            #pragma unroll
            for (int p = 0; p < 4; ++p) {
                uint32_t boff = (uint32_t)((n_base + p * 16 + b_n) * PADK
                                           + kof + b_ko) * 2;
                ldsm_x4(bf[p], sb + TILE_A + boff);
            }
            #pragma unroll
            for (int mt = 0; mt < 4; ++mt) {
                uint32_t aoff = (uint32_t)((m_base + mt * 16 + a_r) * PADK
                                           + kof + a_ko) * 2;
                uint32_t ah[4];
                ldsm_x4(ah, sb + aoff);
                #pragma unroll
                for (int p = 0; p < 4; ++p) {
                    mma_f16(acc[mt][2 * p],     ah, bf[p][0], bf[p][1]);
                    mma_f16(acc[mt][2 * p + 1], ah, bf[p][2], bf[p][3]);
                }
            }
        }
    }

    // ---- epilogue: stage fp16 tile [128][PADE] in smem ----
    __syncthreads();
    {
        const int rq = lid >> 2, cq = (lid & 3) * 2;
        #pragma unroll
        for (int mt = 0; mt < 4; ++mt) {
            #pragma unroll
            for (int nt = 0; nt < 8; ++nt) {
                int col = n_base + nt * 8 + cq;
                int r0 = m_base + mt * 16 + rq;
                *(uint32_t*)(smem + (r0 * PADE + col) * 2) =
                    h2pack(acc[mt][nt][0], acc[mt][nt][1]);
                *(uint32_t*)(smem + ((r0 + 8) * PADE + col) * 2) =
                    h2pack(acc[mt][nt][2], acc[mt][nt][3]);
            }
        }
    }
    __syncthreads();

    if (post == 0) {
        // coalesced 128-bit stores: 16 lanes cover one 128-col row
        const int rbase = tid >> 4, cg = (tid & 15) * 8;
        #pragma unroll
        for (int it = 0; it < 16; ++it) {
            int row = rbase + it * 8;
            uint4 v = *(uint4*)(smem + (row * PADE + cg) * 2);
            *(uint4*)(Out + ((size_t)bm * 128 + row) * Ntot
                          + (size_t)by * 128 + cg) = v;
        }
    } else {
        // GCN: y[n] = relu( sum_m A[n,m] * P[b*4+m] + bias ); Ntot == 1024
        float mat[16];
        #pragma unroll
        for (int i = 0; i < 16; ++i) mat[i] = g_A[i];
        #pragma unroll
        for (int it = 0; it < 4; ++it) {
            int item = it * NTHREADS + tid;   // 0..511 (32 b x 16 ch)
            int b = item >> 4, ch = item & 15;
            int colg = by * 128 + ch * 8;
            float4 bv0 = *(const float4*)(bias + colg);
            float4 bv1 = *(const float4*)(bias + colg + 4);
            float bb[8] = {bv0.x, bv0.y, bv0.z, bv0.w, bv1.x, bv1.y, bv1.z, bv1.w};
            float v[4][8];
            #pragma unroll
            for (int m = 0; m < 4; ++m) {
                uint4 u = *(uint4*)(smem + ((b * 4 + m) * PADE + ch * 8) * 2);
                uint32_t* up = (uint32_t*)&u;
                #pragma unroll
                for (int q = 0; q < 4; ++q) {
                    float2 f = __half22float2(*(__half2*)&up[q]);
                    v[m][q * 2] = f.x; v[m][q * 2 + 1] = f.y;
                }
            }
            #pragma unroll
            for (int n = 0; n < 4; ++n) {
                uint32_t o[4];
                #pragma unroll
                for (int q = 0; q < 4; ++q) {
                    float y0 = fmaxf(mat[n*4+0]*v[0][q*2]   + mat[n*4+1]*v[1][q*2]
                                   + mat[n*4+2]*v[2][q*2]   + mat[n*4+3]*v[3][q*2]
                                   + bb[q*2], 0.f);
                    float y1 = fmaxf(mat[n*4+0]*v[0][q*2+1] + mat[n*4+1]*v[1][q*2+1]
                                   + mat[n*4+2]*v[2][q*2+1] + mat[n*4+3]*v[3][q*2+1]
                                   + bb[q*2+1], 0.f);
                    o[q] = h2pack(y0, y1);
                }
                size_t row = (size_t)bm * 128 + b * 4 + n;
                *(uint4*)(Out + row * 1024 + colg) = *(uint4*)o;
            }
        }
    }
}

// ---------------------------------------------------------------------------
// SAGE post: P[M, 2N] = [Pl | Pr], fp16.  h[b,n,:] =
//   relu( l2norm( Mix.Pl[b,:,:] (row n) + Pr[b,n,:] + bias ) ), fp16 out.
// ---------------------------------------------------------------------------
__global__ void sage_post_kernel(const float* __restrict__ bias, int N)
{
    __shared__ float red[4][4];
    const int b = blockIdx.x, tid = threadIdx.x;
    const int wid = tid >> 5, lane = tid & 31;
    const int nw = blockDim.x >> 5;
    float mat[16];
    #pragma unroll
    for (int i = 0; i < 16; ++i) mat[i] = g_M[i];

    const size_t Pb = (size_t)b * 4 * (2 * N);
    const int f = tid * 4;
    float4 pl[4];
    #pragma unroll
    for (int m = 0; m < 4; ++m)
        pl[m] = load_h4(g_Pf, Pb + (size_t)m * 2 * N + f);
    float4 bv = *(const float4*)(bias + f);

    float4 y[4];
    float ss[4];
    #pragma unroll
    for (int n = 0; n < 4; ++n) {
        float4 pr = load_h4(g_Pf, Pb + (size_t)n * 2 * N + N + f);
        float4 r;
        r.x = mat[n*4+0]*pl[0].x + mat[n*4+1]*pl[1].x + mat[n*4+2]*pl[2].x + mat[n*4+3]*pl[3].x + pr.x + bv.x;
        r.y = mat[n*4+0]*pl[0].y + mat[n*4+1]*pl[1].y + mat[n*4+2]*pl[2].y + mat[n*4+3]*pl[3].y + pr.y + bv.y;
        r.z = mat[n*4+0]*pl[0].z + mat[n*4+1]*pl[1].z + mat[n*4+2]*pl[2].z + mat[n*4+3]*pl[3].z + pr.z + bv.z;
        r.w = mat[n*4+0]*pl[0].w + mat[n*4+1]*pl[1].w + mat[n*4+2]*pl[2].w + mat[n*4+3]*pl[3].w + pr.w + bv.w;
        y[n] = r;
        ss[n] = r.x * r.x + r.y * r.y + r.z * r.z + r.w * r.w;
    }
    #pragma unroll
    for (int n = 0; n < 4; ++n)
        #pragma unroll
        for (int off = 16; off > 0; off >>= 1)
            ss[n] += __shfl_xor_sync(0xffffffffu, ss[n], off);
    if (lane == 0) {
        #pragma unroll
        for (int n = 0; n < 4; ++n) red[n][wid] = ss[n];
    }
    __syncthreads();
    float inv[4];
    #pragma unroll
    for (int n = 0; n < 4; ++n) {
        float t = 0.f;
        for (int w = 0; w < nw; ++w) t += red[n][w];
        inv[n] = 1.f / fmaxf(sqrtf(t), 1e-12f);
    }
    #pragma unroll
    for (int n = 0; n < 4; ++n) {
        float4 o;
        o.x = fmaxf(y[n].x * inv[n], 0.f);
        o.y = fmaxf(y[n].y * inv[n], 0.f);
        o.z = fmaxf(y[n].z * inv[n], 0.f);
        o.w = fmaxf(y[n].w * inv[n], 0.f);
        store_h4(g_hf, (size_t)(b * 4 + n) * N + f, o);
    }
}

// ---------------------------------------------------------------------------
// FC [B,1024] @ Wfc[1024,10] + bfc, softmax. One warp per batch row.
// ---------------------------------------------------------------------------
__global__ void fc_softmax_kernel(const float* __restrict__ Wfc,
                                  const float* __restrict__ bfc,
                                  float* __restrict__ out, int B)
{
    long long warp = ((long long)blockIdx.x * blockDim.x + threadIdx.x) >> 5;
    int lane = threadIdx.x & 31;
    if (warp >= B) return;
    const size_t base = (size_t)warp * 1024;
    float acc[10];
    #pragma unroll
    for (int o = 0; o < 10; ++o) acc[o] = 0.f;
    for (int k = lane; k < 1024; k += 32) {
        float hv = __half2float(g_hf[base + k]);
        const float* w = Wfc + (size_t)k * 10;
        #pragma unroll
        for (int o = 0; o < 10; ++o) acc[o] += hv * w[o];
    }
    #pragma unroll
    for (int o = 0; o < 10; ++o)
        #pragma unroll
        for (int off = 16; off > 0; off >>= 1)
            acc[o] += __shfl_xor_sync(0xffffffffu, acc[o], off);
    if (lane == 0) {
        float logit[10], m = -1e30f;
        #pragma unroll
        for (int o = 0; o < 10; ++o) {
            logit[o] = acc[o] + bfc[o];
            m = fmaxf(m, logit[o]);
        }
        float s = 0.f;
        #pragma unroll
        for (int o = 0; o < 10; ++o) { logit[o] = expf(logit[o] - m); s += logit[o]; }
        float invs = 1.f / s;
        float* orow = out + (size_t)warp * 10;
        #pragma unroll
        for (int o = 0; o < 10; ++o) orow[o] = logit[o] * invs;
    }
}

// ---------------------------------------------------------------------------
extern "C" void kernel_launch(void* const* d_in, const int* in_sizes, int n_in,
                              void* d_out, int out_size)
{
    const float* x   = (const float*)d_in[0];
    const void*  ei  = d_in[1];
    const float* W1  = (const float*)d_in[2];
    const float* b1  = (const float*)d_in[3];
    const float* Wl2 = (const float*)d_in[4];
    const float* bl2 = (const float*)d_in[5];
    const float* Wr2 = (const float*)d_in[6];
    const float* Wl3 = (const float*)d_in[7];
    const float* bl3 = (const float*)d_in[8];
    const float* Wr3 = (const float*)d_in[9];
    const float* Wl4 = (const float*)d_in[10];
    const float* bl4 = (const float*)d_in[11];
    const float* Wr4 = (const float*)d_in[12];
    const float* Wfc = (const float*)d_in[13];
    const float* bfc = (const float*)d_in[14];

    const int B = in_sizes[0] / (4 * 64);
    const int E = in_sizes[1] / 2;
    const long long M = (long long)B * 4;

    __half *Pf, *hf;
    cudaGetSymbolAddress((void**)&Pf, g_Pf);
    cudaGetSymbolAddress((void**)&hf, g_hf);

    cudaFuncSetAttribute(gemm_tc_kernel,
                         cudaFuncAttributeMaxDynamicSharedMemorySize, SMEM_BYTES);

    build_graph_kernel<<<1, 32>>>(ei, E);

    // weight prep: N-concat layout [Ntot][K0], offsets in fp16 elements
    const size_t OW1 = 0;                       // [1024][64]
    const size_t OW2 = 65536;                   // [1024][1024] = [Wl2|Wr2]
    const size_t OW3 = OW2 + 1048576;           // [512][512]  = [Wl3|Wr3]
    const size_t OW4 = OW3 + 262144;            // [512][256]  = [Wl4|Wr4]
    prep_w_kernel<<<(64   * 1024 + 255) / 256, 256>>>(W1,  64,   1024, OW1);
    prep_w_kernel<<<(1024 * 512  + 255) / 256, 256>>>(Wl2, 1024, 512,  OW2);
    prep_w_kernel<<<(1024 * 512  + 255) / 256, 256>>>(Wr2, 1024, 512,  OW2 + (size_t)512 * 1024);
    prep_w_kernel<<<(512  * 256  + 255) / 256, 256>>>(Wl3, 512,  256,  OW3);
    prep_w_kernel<<<(512  * 256  + 255) / 256, 256>>>(Wr3, 512,  256,  OW3 + (size_t)256 * 512);
    prep_w_kernel<<<(256  * 256  + 255) / 256, 256>>>(Wl4, 256,  256,  OW4);
    prep_w_kernel<<<(256  * 256  + 255) / 256, 256>>>(Wr4, 256,  256,  OW4 + (size_t)256 * 256);

    const unsigned gm = (unsigned)(M / 128);

    // x -> fp16 (into g_Pf, the L1 GEMM input)
    split_x_kernel<<<(unsigned)((M * 16 + 255) / 256), 256>>>(x, M * 16);
    // L1: h1 = relu(Mix.(x@W1) + b1) — GCN fused epilogue
    gemm_tc_kernel<<<dim3(8, gm), NTHREADS, SMEM_BYTES>>>(Pf, OW1, hf, b1, 64, 1024, 1);
    // L2: P2 = h1 @ [Wl2|Wr2] [M,1024];  h2 = sage_post(P2) [M,512]
    gemm_tc_kernel<<<dim3(8, gm), NTHREADS, SMEM_BYTES>>>(hf, OW2, Pf, b1, 1024, 1024, 0);
    sage_post_kernel<<<B, 128>>>(bl2, 512);
    // L3: P3 = h2 @ [Wl3|Wr3] [M,512];  h3 [M,256]
    gemm_tc_kernel<<<dim3(4, gm), NTHREADS, SMEM_BYTES>>>(hf, OW3, Pf, b1, 512, 512, 0);
    sage_post_kernel<<<B, 64>>>(bl3, 256);
    // L4: P4 = h3 @ [Wl4|Wr4] [M,512];  h4 [M,256]
    gemm_tc_kernel<<<dim3(4, gm), NTHREADS, SMEM_BYTES>>>(hf, OW4, Pf, b1, 256, 512, 0);
    sage_post_kernel<<<B, 64>>>(bl4, 256);
    // FC + softmax
    fc_softmax_kernel<<<(unsigned)((B * 32 + 255) / 256), 256>>>(
        Wfc, bfc, (float*)d_out, B);
}